// round 1
// baseline (speedup 1.0000x reference)
#include <cuda_runtime.h>
#include <math.h>

#define NN 50000
#define NE 500000
#define H  256
#define NL 15

// ---- scratch (device globals; no allocations allowed) ----
static __device__ float  g_h[(size_t)NN * H];     // carry / final h
static __device__ float  g_agg[(size_t)NN * H];   // per-layer aggregate; later P = h@W1a^T
static __device__ float  g_tmp[(size_t)NN * H];   // pre-BN out;        later Q = h@W1b^T
static __device__ double g_stats[2 * H];          // column sum / sumsq
static __device__ float  g_bnp[2 * H];            // scale / offset
static __device__ float  g_acc[NE];               // pre-sigmoid edge accumulator

typedef unsigned long long u64;

__device__ __forceinline__ u64 pk2(float lo, float hi) {
    u64 r; asm("mov.b64 %0, {%1, %2};" : "=l"(r) : "f"(lo), "f"(hi)); return r;
}
__device__ __forceinline__ void fma2(u64 &c, u64 a, u64 b) {
    asm("fma.rn.f32x2 %0, %1, %2, %0;" : "+l"(c) : "l"(a), "l"(b));
}
__device__ __forceinline__ void upk(u64 v, float &a, float &b) {
    asm("mov.b64 {%0, %1}, %2;" : "=f"(a), "=f"(b) : "l"(v));
}

// ---- h = x @ W_in^T ; also zero agg ----
__global__ void input_fc_kernel(const float* __restrict__ x, const float* __restrict__ Win,
                                float* __restrict__ h, float* __restrict__ agg) {
    __shared__ float w0[H], w1[H];
    int tid = threadIdx.x;
    w0[tid] = Win[tid * 2];
    w1[tid] = Win[tid * 2 + 1];
    __syncthreads();
    int idx = blockIdx.x * 256 + tid;            // over NN*64 float4 slots
    if (idx < NN * 64) {
        int n = idx >> 6;
        int j = (idx & 63) * 4;
        float2 xv = *(const float2*)(x + (size_t)n * 2);
        float4 o;
        o.x = xv.x * w0[j + 0] + xv.y * w1[j + 0];
        o.y = xv.x * w0[j + 1] + xv.y * w1[j + 1];
        o.z = xv.x * w0[j + 2] + xv.y * w1[j + 2];
        o.w = xv.x * w0[j + 3] + xv.y * w1[j + 3];
        ((float4*)h)[idx] = o;
        ((float4*)agg)[idx] = make_float4(0.f, 0.f, 0.f, 0.f);
    }
}

__global__ void zero_acc_kernel(float* __restrict__ acc) {
    int i = blockIdx.x * 256 + threadIdx.x;
    if (i < NE) acc[i] = 0.f;
}

// ---- scatter-add: agg[dst] += h[src], 64 threads per edge ----
__global__ void scatter_kernel(const float* __restrict__ h, float* __restrict__ agg,
                               const int* __restrict__ src, const int* __restrict__ dst) {
    int t = blockIdx.x * 256 + threadIdx.x;
    int e = t >> 6;
    int lane = t & 63;
    int s = src[e];
    int d = dst[e];
    float4 v = *(const float4*)(h + (size_t)s * H + lane * 4);
    float* p = agg + (size_t)d * H + lane * 4;
    atomicAdd(p + 0, v.x);
    atomicAdd(p + 1, v.y);
    atomicAdd(p + 2, v.z);
    atomicAdd(p + 3, v.w);
}

// ---- tiled GEMM, BM=128 BN=64 BK=16, f32x2 packed accumulators ----
// AMODE 0: A[m][k] = (k<256 ? A0 : A1)[row][k%256], row = m0+m (clamped)
// AMODE 2: A[m][k] = relu(A0[idx0[m]][k] + A1[idx1[m]][k] + biasA[k])   (K=256)
// EPI 0: C = acc + bias      EPI 1: C = relu(acc+bias)
// EPI 2: accOut[row] += sum_j relu(acc+bias)[j] * w3[j]   (shuffle-reduced)
template<int AMODE, int EPI, int KT>
__global__ void __launch_bounds__(256) gemm_kernel(
    const float* __restrict__ A0, const float* __restrict__ A1,
    const int* __restrict__ idx0, const int* __restrict__ idx1,
    const float* __restrict__ biasA,
    const float* __restrict__ B0, const float* __restrict__ B1, int bstride,
    const float* __restrict__ bias,
    float* __restrict__ C, int M,
    const float* __restrict__ w3, float* __restrict__ accOut)
{
    __shared__ __align__(16) float As[16][132];
    __shared__ __align__(16) float Bs[16][68];
    __shared__ int sIdx[2][128];
    const int tid = threadIdx.x;
    const int tx = tid & 15, ty = tid >> 4;
    const int m0 = blockIdx.x * 128;
    const int j0 = blockIdx.y * 64;

    if (AMODE == 2) {
        if (tid < 128) {
            int r = min(m0 + tid, M - 1);
            sIdx[0][tid] = idx0[r];
            sIdx[1][tid] = idx1[r];
        }
        __syncthreads();
    }

    u64 acc[4][4];
    #pragma unroll
    for (int i = 0; i < 4; i++)
        #pragma unroll
        for (int j = 0; j < 4; j++) acc[i][j] = 0ull;

    const int bm  = tid >> 2;   // 0..63
    const int bkv = tid & 3;    // 0..3

    for (int kt = 0; kt < KT; ++kt) {
        const int kk0 = kt * 16;
        const int phase = (kk0 >= 256) ? 1 : 0;
        const int kof = kk0 - (phase << 8);
        // load A tile (transposed into As[k][m])
        #pragma unroll
        for (int q = 0; q < 2; q++) {
            int m = bm + q * 64;
            float4 v;
            if (AMODE == 0) {
                const float* Ap = phase ? A1 : A0;
                int r = min(m0 + m, M - 1);
                v = *(const float4*)(Ap + (size_t)r * H + kof + bkv * 4);
            } else {
                int rs = sIdx[0][m], rd = sIdx[1][m];
                float4 p  = *(const float4*)(A0 + (size_t)rs * H + kof + bkv * 4);
                float4 qq = *(const float4*)(A1 + (size_t)rd * H + kof + bkv * 4);
                float4 bb = *(const float4*)(biasA + kof + bkv * 4);
                v.x = fmaxf(p.x + qq.x + bb.x, 0.f);
                v.y = fmaxf(p.y + qq.y + bb.y, 0.f);
                v.z = fmaxf(p.z + qq.z + bb.z, 0.f);
                v.w = fmaxf(p.w + qq.w + bb.w, 0.f);
            }
            As[bkv * 4 + 0][m] = v.x;
            As[bkv * 4 + 1][m] = v.y;
            As[bkv * 4 + 2][m] = v.z;
            As[bkv * 4 + 3][m] = v.w;
        }
        // load B tile (B row-major [j][k], transposed into Bs[k][j])
        {
            const float* Bp = phase ? B1 : B0;
            float4 v = *(const float4*)(Bp + (size_t)(j0 + bm) * bstride + kof + bkv * 4);
            Bs[bkv * 4 + 0][bm] = v.x;
            Bs[bkv * 4 + 1][bm] = v.y;
            Bs[bkv * 4 + 2][bm] = v.z;
            Bs[bkv * 4 + 3][bm] = v.w;
        }
        __syncthreads();
        #pragma unroll
        for (int kk = 0; kk < 16; ++kk) {
            const ulonglong2* ap = (const ulonglong2*)(&As[kk][ty * 8]);
            ulonglong2 aA = ap[0], aB = ap[1];
            u64 ar[4] = { aA.x, aA.y, aB.x, aB.y };
            float4 b = *(const float4*)(&Bs[kk][tx * 4]);
            u64 bd[4] = { pk2(b.x, b.x), pk2(b.y, b.y), pk2(b.z, b.z), pk2(b.w, b.w) };
            #pragma unroll
            for (int j = 0; j < 4; j++)
                #pragma unroll
                for (int i = 0; i < 4; i++)
                    fma2(acc[i][j], ar[i], bd[j]);
        }
        __syncthreads();
    }

    float c[8][4];
    #pragma unroll
    for (int i = 0; i < 4; i++)
        #pragma unroll
        for (int j = 0; j < 4; j++)
            upk(acc[i][j], c[2 * i][j], c[2 * i + 1][j]);

    if (EPI <= 1) {
        float4 bs = make_float4(0.f, 0.f, 0.f, 0.f);
        if (bias) bs = *(const float4*)(bias + j0 + tx * 4);
        #pragma unroll
        for (int i = 0; i < 8; i++) {
            int r = m0 + ty * 8 + i;
            if (r < M) {
                float4 o;
                o.x = c[i][0] + bs.x; o.y = c[i][1] + bs.y;
                o.z = c[i][2] + bs.z; o.w = c[i][3] + bs.w;
                if (EPI == 1) {
                    o.x = fmaxf(o.x, 0.f); o.y = fmaxf(o.y, 0.f);
                    o.z = fmaxf(o.z, 0.f); o.w = fmaxf(o.w, 0.f);
                }
                *(float4*)(C + (size_t)r * H + j0 + tx * 4) = o;
            }
        }
    } else {
        float4 bs = *(const float4*)(bias + j0 + tx * 4);
        float4 wv = *(const float4*)(w3 + j0 + tx * 4);
        #pragma unroll
        for (int i = 0; i < 8; i++) {
            float p = fmaxf(c[i][0] + bs.x, 0.f) * wv.x
                    + fmaxf(c[i][1] + bs.y, 0.f) * wv.y
                    + fmaxf(c[i][2] + bs.z, 0.f) * wv.z
                    + fmaxf(c[i][3] + bs.w, 0.f) * wv.w;
            p += __shfl_xor_sync(0xffffffffu, p, 1);
            p += __shfl_xor_sync(0xffffffffu, p, 2);
            p += __shfl_xor_sync(0xffffffffu, p, 4);
            p += __shfl_xor_sync(0xffffffffu, p, 8);
            int r = m0 + ty * 8 + i;
            if (tx == 0 && r < M) atomicAdd(accOut + r, p);
        }
    }
}

// ---- BN statistics ----
__global__ void zero_stats_kernel() {
    g_stats[threadIdx.x] = 0.0;
}

__global__ void colstats_kernel(const float* __restrict__ T) {
    int j = threadIdx.x;
    int r0 = blockIdx.x * 196;
    int r1 = min(r0 + 196, NN);
    double s = 0.0, s2 = 0.0;
    for (int r = r0; r < r1; r++) {
        float v = T[(size_t)r * H + j];
        s += (double)v;
        s2 += (double)v * (double)v;
    }
    atomicAdd(&g_stats[j], s);
    atomicAdd(&g_stats[H + j], s2);
}

__global__ void bn_prep_kernel(const float* __restrict__ gamma, const float* __restrict__ beta) {
    int j = threadIdx.x;
    double mean = g_stats[j] * (1.0 / NN);
    double var  = g_stats[H + j] * (1.0 / NN) - mean * mean;
    double inv  = 1.0 / sqrt(var + 1e-5);
    double sc   = (double)gamma[j] * inv;
    g_bnp[j]     = (float)sc;
    g_bnp[H + j] = (float)((double)beta[j] - mean * sc);
}

// carry += relu(T*scale + offset); also zero agg for next layer
__global__ void bn_apply_kernel(float* __restrict__ carry, const float* __restrict__ T,
                                float* __restrict__ agg) {
    int idx = blockIdx.x * 256 + threadIdx.x;   // NN*64 float4 slots
    if (idx >= NN * 64) return;
    int j = (idx & 63) * 4;
    float4 t  = ((const float4*)T)[idx];
    float4 cv = ((float4*)carry)[idx];
    cv.x += fmaxf(t.x * g_bnp[j + 0] + g_bnp[H + j + 0], 0.f);
    cv.y += fmaxf(t.y * g_bnp[j + 1] + g_bnp[H + j + 1], 0.f);
    cv.z += fmaxf(t.z * g_bnp[j + 2] + g_bnp[H + j + 2], 0.f);
    cv.w += fmaxf(t.w * g_bnp[j + 3] + g_bnp[H + j + 3], 0.f);
    ((float4*)carry)[idx] = cv;
    ((float4*)agg)[idx] = make_float4(0.f, 0.f, 0.f, 0.f);
}

__global__ void final_kernel(const float* __restrict__ b3, float* __restrict__ out) {
    int i = blockIdx.x * 256 + threadIdx.x;
    if (i < NE) {
        float v = g_acc[i] + b3[0];
        out[i] = 1.f / (1.f + expf(-v));
    }
}

extern "C" void kernel_launch(void* const* d_in, const int* in_sizes, int n_in,
                              void* d_out, int out_size) {
    const float* x     = (const float*)d_in[0];
    const int*   ei    = (const int*)  d_in[1];
    const float* Win   = (const float*)d_in[2];
    const float* Wrel  = (const float*)d_in[3];
    const float* brel  = (const float*)d_in[4];
    const float* Wroot = (const float*)d_in[5];
    const float* gamma = (const float*)d_in[6];
    const float* beta  = (const float*)d_in[7];
    const float* W1    = (const float*)d_in[8];
    const float* b1    = (const float*)d_in[9];
    const float* W2    = (const float*)d_in[10];
    const float* b2    = (const float*)d_in[11];
    const float* W3    = (const float*)d_in[12];
    const float* b3    = (const float*)d_in[13];
    float* out = (float*)d_out;

    float *h, *agg, *tmp, *acc;
    cudaGetSymbolAddress((void**)&h,   g_h);
    cudaGetSymbolAddress((void**)&agg, g_agg);
    cudaGetSymbolAddress((void**)&tmp, g_tmp);
    cudaGetSymbolAddress((void**)&acc, g_acc);

    const int* src = ei;
    const int* dst = ei + NE;

    input_fc_kernel<<<NN * 64 / 256, 256>>>(x, Win, h, agg);
    zero_acc_kernel<<<(NE + 255) / 256, 256>>>(acc);

    for (int l = 0; l < NL; l++) {
        scatter_kernel<<<NE / 4, 256>>>(h, agg, src, dst);
        gemm_kernel<0, 0, 32><<<dim3(391, 4), 256>>>(
            agg, h, nullptr, nullptr, nullptr,
            Wrel + (size_t)l * H * H, Wroot + (size_t)l * H * H, H,
            brel + l * H, tmp, NN, nullptr, nullptr);
        zero_stats_kernel<<<1, 512>>>();
        colstats_kernel<<<256, 256>>>(tmp);
        bn_prep_kernel<<<1, 256>>>(gamma + l * H, beta + l * H);
        bn_apply_kernel<<<NN * 64 / 256, 256>>>(h, tmp, agg);
    }

    // P = h @ W1[:, :256]^T  -> agg ;  Q = h @ W1[:, 256:]^T -> tmp
    gemm_kernel<0, 0, 16><<<dim3(391, 4), 256>>>(
        h, h, nullptr, nullptr, nullptr, W1, W1, 2 * H, nullptr, agg, NN, nullptr, nullptr);
    gemm_kernel<0, 0, 16><<<dim3(391, 4), 256>>>(
        h, h, nullptr, nullptr, nullptr, W1 + H, W1 + H, 2 * H, nullptr, tmp, NN, nullptr, nullptr);

    // fused: z1 = relu(P[src]+Q[dst]+b1); z2 = relu(z1@W2^T + b2); acc += z2 . w3
    gemm_kernel<2, 2, 16><<<dim3((NE + 127) / 128, 4), 256>>>(
        agg, tmp, src, dst, b1, W2, W2, H, b2, nullptr, NE, W3, acc);

    final_kernel<<<(NE + 255) / 256, 256>>>(b3, out);
}

// round 2
// speedup vs baseline: 1.6961x; 1.6961x over previous
#include <cuda_runtime.h>
#include <math.h>

#define NN 50000
#define NE 500000
#define H  256
#define NL 15

// ---- scratch (device globals; no allocations allowed) ----
static __device__ float  g_h[(size_t)NN * H];     // carry / final h
static __device__ float  g_agg[(size_t)NN * H];   // per-layer aggregate; later P = h@W1a^T
static __device__ float  g_tmp[(size_t)NN * H];   // pre-BN out;        later Q = h@W1b^T
static __device__ double g_stats[2 * H];          // column sum / sumsq
static __device__ float  g_bnp[2 * H];            // scale / offset
static __device__ float  g_acc[NE];               // pre-sigmoid edge accumulator
static __device__ int    g_cnt[NN];               // in-degree histogram
static __device__ int    g_rowptr[NN + 1];        // CSR row pointers
static __device__ int    g_cursor[NN];            // fill cursors
static __device__ int    g_csrsrc[NE];            // CSR column (source node) array

typedef unsigned long long u64;

__device__ __forceinline__ u64 pk2(float lo, float hi) {
    u64 r; asm("mov.b64 %0, {%1, %2};" : "=l"(r) : "f"(lo), "f"(hi)); return r;
}
__device__ __forceinline__ void fma2(u64 &c, u64 a, u64 b) {
    asm("fma.rn.f32x2 %0, %1, %2, %0;" : "+l"(c) : "l"(a), "l"(b));
}
__device__ __forceinline__ void upk(u64 v, float &a, float &b) {
    asm("mov.b64 {%0, %1}, %2;" : "=f"(a), "=f"(b) : "l"(v));
}

// ================= CSR construction (once per launch) =================
__global__ void zero_cnt_kernel() {
    int i = blockIdx.x * 256 + threadIdx.x;
    if (i < NN) g_cnt[i] = 0;
}
__global__ void hist_kernel(const int* __restrict__ dst) {
    int e = blockIdx.x * 256 + threadIdx.x;
    if (e < NE) atomicAdd(&g_cnt[dst[e]], 1);
}
// single-block exclusive scan over 50000 counts (chunked Hillis-Steele)
__global__ void scan_kernel() {
    __shared__ int partial[1024];
    const int CH = (NN + 1023) / 1024;  // 49
    int t = threadIdx.x;
    int base = t * CH;
    int s = 0;
    for (int i = 0; i < CH; i++) {
        int idx = base + i;
        if (idx < NN) s += g_cnt[idx];
    }
    partial[t] = s;
    __syncthreads();
    for (int off = 1; off < 1024; off <<= 1) {
        int v = (t >= off) ? partial[t - off] : 0;
        __syncthreads();
        partial[t] += v;
        __syncthreads();
    }
    int ex = partial[t] - s;   // exclusive prefix of this chunk
    for (int i = 0; i < CH; i++) {
        int idx = base + i;
        if (idx < NN) {
            g_rowptr[idx] = ex;
            g_cursor[idx] = ex;
            ex += g_cnt[idx];
        }
    }
    if (t == 1023) g_rowptr[NN] = NE;
}
__global__ void fill_kernel(const int* __restrict__ src, const int* __restrict__ dst) {
    int e = blockIdx.x * 256 + threadIdx.x;
    if (e < NE) {
        int pos = atomicAdd(&g_cursor[dst[e]], 1);
        g_csrsrc[pos] = src[e];
    }
}

// ---- h = x @ W_in^T ----
__global__ void input_fc_kernel(const float* __restrict__ x, const float* __restrict__ Win,
                                float* __restrict__ h) {
    __shared__ float w0[H], w1[H];
    int tid = threadIdx.x;
    w0[tid] = Win[tid * 2];
    w1[tid] = Win[tid * 2 + 1];
    __syncthreads();
    int idx = blockIdx.x * 256 + tid;            // over NN*64 float4 slots
    if (idx < NN * 64) {
        int n = idx >> 6;
        int j = (idx & 63) * 4;
        float2 xv = *(const float2*)(x + (size_t)n * 2);
        float4 o;
        o.x = xv.x * w0[j + 0] + xv.y * w1[j + 0];
        o.y = xv.x * w0[j + 1] + xv.y * w1[j + 1];
        o.z = xv.x * w0[j + 2] + xv.y * w1[j + 2];
        o.w = xv.x * w0[j + 3] + xv.y * w1[j + 3];
        ((float4*)h)[idx] = o;
    }
}

__global__ void zero_acc_kernel(float* __restrict__ acc) {
    int i = blockIdx.x * 256 + threadIdx.x;
    if (i < NE) acc[i] = 0.f;
}

// ---- CSR aggregation: agg[n] = sum over in-edges of h[src] (no atomics) ----
__global__ void aggregate_kernel(const float* __restrict__ h, float* __restrict__ agg) {
    int t = blockIdx.x * 256 + threadIdx.x;
    int node = t >> 6;
    int lane = t & 63;
    if (node >= NN) return;
    int b = g_rowptr[node], e = g_rowptr[node + 1];
    float4 s = make_float4(0.f, 0.f, 0.f, 0.f);
    for (int j = b; j < e; j++) {
        int sn = __ldg(g_csrsrc + j);
        float4 v = __ldg((const float4*)(h + (size_t)sn * H) + lane);
        s.x += v.x; s.y += v.y; s.z += v.z; s.w += v.w;
    }
    ((float4*)(agg + (size_t)node * H))[lane] = s;
}

// ---- tiled GEMM, BM=128 BN=64 BK=16, f32x2 packed accumulators ----
// AMODE 0: A[m][k] = (k<256 ? A0 : A1)[row][k%256], row = m0+m (clamped)
// AMODE 2: A[m][k] = relu(A0[idx0[m]][k] + A1[idx1[m]][k] + biasA[k])   (K=256)
// EPI 0: C = acc + bias      EPI 1: C = relu(acc+bias)
// EPI 2: accOut[row] += sum_j relu(acc+bias)[j] * w3[j]   (shuffle-reduced)
// STATS 1: also accumulate per-column sum/sumsq of C into g_stats (for BN)
template<int AMODE, int EPI, int KT, int STATS>
__global__ void __launch_bounds__(256) gemm_kernel(
    const float* __restrict__ A0, const float* __restrict__ A1,
    const int* __restrict__ idx0, const int* __restrict__ idx1,
    const float* __restrict__ biasA,
    const float* __restrict__ B0, const float* __restrict__ B1, int bstride,
    const float* __restrict__ bias,
    float* __restrict__ C, int M,
    const float* __restrict__ w3, float* __restrict__ accOut)
{
    __shared__ __align__(16) float As[16][132];
    __shared__ __align__(16) float Bs[16][68];
    __shared__ int sIdx[2][128];
    const int tid = threadIdx.x;
    const int tx = tid & 15, ty = tid >> 4;
    const int m0 = blockIdx.x * 128;
    const int j0 = blockIdx.y * 64;

    if (AMODE == 2) {
        if (tid < 128) {
            int r = min(m0 + tid, M - 1);
            sIdx[0][tid] = idx0[r];
            sIdx[1][tid] = idx1[r];
        }
        __syncthreads();
    }

    u64 acc[4][4];
    #pragma unroll
    for (int i = 0; i < 4; i++)
        #pragma unroll
        for (int j = 0; j < 4; j++) acc[i][j] = 0ull;

    const int bm  = tid >> 2;   // 0..63
    const int bkv = tid & 3;    // 0..3

    for (int kt = 0; kt < KT; ++kt) {
        const int kk0 = kt * 16;
        const int phase = (kk0 >= 256) ? 1 : 0;
        const int kof = kk0 - (phase << 8);
        // load A tile (transposed into As[k][m])
        #pragma unroll
        for (int q = 0; q < 2; q++) {
            int m = bm + q * 64;
            float4 v;
            if (AMODE == 0) {
                const float* Ap = phase ? A1 : A0;
                int r = min(m0 + m, M - 1);
                v = *(const float4*)(Ap + (size_t)r * H + kof + bkv * 4);
            } else {
                int rs = sIdx[0][m], rd = sIdx[1][m];
                float4 p  = *(const float4*)(A0 + (size_t)rs * H + kof + bkv * 4);
                float4 qq = *(const float4*)(A1 + (size_t)rd * H + kof + bkv * 4);
                float4 bb = *(const float4*)(biasA + kof + bkv * 4);
                v.x = fmaxf(p.x + qq.x + bb.x, 0.f);
                v.y = fmaxf(p.y + qq.y + bb.y, 0.f);
                v.z = fmaxf(p.z + qq.z + bb.z, 0.f);
                v.w = fmaxf(p.w + qq.w + bb.w, 0.f);
            }
            As[bkv * 4 + 0][m] = v.x;
            As[bkv * 4 + 1][m] = v.y;
            As[bkv * 4 + 2][m] = v.z;
            As[bkv * 4 + 3][m] = v.w;
        }
        // load B tile (B row-major [j][k], transposed into Bs[k][j])
        {
            const float* Bp = phase ? B1 : B0;
            float4 v = *(const float4*)(Bp + (size_t)(j0 + bm) * bstride + kof + bkv * 4);
            Bs[bkv * 4 + 0][bm] = v.x;
            Bs[bkv * 4 + 1][bm] = v.y;
            Bs[bkv * 4 + 2][bm] = v.z;
            Bs[bkv * 4 + 3][bm] = v.w;
        }
        __syncthreads();
        #pragma unroll
        for (int kk = 0; kk < 16; ++kk) {
            const ulonglong2* ap = (const ulonglong2*)(&As[kk][ty * 8]);
            ulonglong2 aA = ap[0], aB = ap[1];
            u64 ar[4] = { aA.x, aA.y, aB.x, aB.y };
            float4 b = *(const float4*)(&Bs[kk][tx * 4]);
            u64 bd[4] = { pk2(b.x, b.x), pk2(b.y, b.y), pk2(b.z, b.z), pk2(b.w, b.w) };
            #pragma unroll
            for (int j = 0; j < 4; j++)
                #pragma unroll
                for (int i = 0; i < 4; i++)
                    fma2(acc[i][j], ar[i], bd[j]);
        }
        __syncthreads();
    }

    float c[8][4];
    #pragma unroll
    for (int i = 0; i < 4; i++)
        #pragma unroll
        for (int j = 0; j < 4; j++)
            upk(acc[i][j], c[2 * i][j], c[2 * i + 1][j]);

    if (EPI <= 1) {
        float4 bs = make_float4(0.f, 0.f, 0.f, 0.f);
        if (bias) bs = *(const float4*)(bias + j0 + tx * 4);
        float colS[4] = {0.f, 0.f, 0.f, 0.f};
        float colQ[4] = {0.f, 0.f, 0.f, 0.f};
        #pragma unroll
        for (int i = 0; i < 8; i++) {
            int r = m0 + ty * 8 + i;
            if (r < M) {
                float4 o;
                o.x = c[i][0] + bs.x; o.y = c[i][1] + bs.y;
                o.z = c[i][2] + bs.z; o.w = c[i][3] + bs.w;
                if (EPI == 1) {
                    o.x = fmaxf(o.x, 0.f); o.y = fmaxf(o.y, 0.f);
                    o.z = fmaxf(o.z, 0.f); o.w = fmaxf(o.w, 0.f);
                }
                *(float4*)(C + (size_t)r * H + j0 + tx * 4) = o;
                if (STATS) {
                    colS[0] += o.x; colS[1] += o.y; colS[2] += o.z; colS[3] += o.w;
                    colQ[0] += o.x * o.x; colQ[1] += o.y * o.y;
                    colQ[2] += o.z * o.z; colQ[3] += o.w * o.w;
                }
            }
        }
        if (STATS) {
            __shared__ float sSum[16][64];
            __shared__ float sSq[16][64];
            __syncthreads();   // done with As/Bs; also orders sSum writes
            #pragma unroll
            for (int cidx = 0; cidx < 4; cidx++) {
                sSum[ty][tx * 4 + cidx] = colS[cidx];
                sSq[ty][tx * 4 + cidx]  = colQ[cidx];
            }
            __syncthreads();
            if (tid < 64) {
                float ts = 0.f, tq = 0.f;
                #pragma unroll
                for (int yy = 0; yy < 16; yy++) {
                    ts += sSum[yy][tid];
                    tq += sSq[yy][tid];
                }
                atomicAdd(&g_stats[j0 + tid], (double)ts);
                atomicAdd(&g_stats[H + j0 + tid], (double)tq);
            }
        }
    } else {
        float4 bs = *(const float4*)(bias + j0 + tx * 4);
        float4 wv = *(const float4*)(w3 + j0 + tx * 4);
        #pragma unroll
        for (int i = 0; i < 8; i++) {
            float p = fmaxf(c[i][0] + bs.x, 0.f) * wv.x
                    + fmaxf(c[i][1] + bs.y, 0.f) * wv.y
                    + fmaxf(c[i][2] + bs.z, 0.f) * wv.z
                    + fmaxf(c[i][3] + bs.w, 0.f) * wv.w;
            p += __shfl_xor_sync(0xffffffffu, p, 1);
            p += __shfl_xor_sync(0xffffffffu, p, 2);
            p += __shfl_xor_sync(0xffffffffu, p, 4);
            p += __shfl_xor_sync(0xffffffffu, p, 8);
            int r = m0 + ty * 8 + i;
            if (tx == 0 && r < M) atomicAdd(accOut + r, p);
        }
    }
}

// ---- BN ----
__global__ void zero_stats_kernel() {
    g_stats[threadIdx.x] = 0.0;
}

__global__ void bn_prep_kernel(const float* __restrict__ gamma, const float* __restrict__ beta) {
    int j = threadIdx.x;
    double mean = g_stats[j] * (1.0 / NN);
    double var  = g_stats[H + j] * (1.0 / NN) - mean * mean;
    double inv  = 1.0 / sqrt(var + 1e-5);
    double sc   = (double)gamma[j] * inv;
    g_bnp[j]     = (float)sc;
    g_bnp[H + j] = (float)((double)beta[j] - mean * sc);
}

// carry += relu(T*scale + offset)
__global__ void bn_apply_kernel(float* __restrict__ carry, const float* __restrict__ T) {
    int idx = blockIdx.x * 256 + threadIdx.x;   // NN*64 float4 slots
    if (idx >= NN * 64) return;
    int j = (idx & 63) * 4;
    float4 t  = ((const float4*)T)[idx];
    float4 cv = ((float4*)carry)[idx];
    cv.x += fmaxf(t.x * g_bnp[j + 0] + g_bnp[H + j + 0], 0.f);
    cv.y += fmaxf(t.y * g_bnp[j + 1] + g_bnp[H + j + 1], 0.f);
    cv.z += fmaxf(t.z * g_bnp[j + 2] + g_bnp[H + j + 2], 0.f);
    cv.w += fmaxf(t.w * g_bnp[j + 3] + g_bnp[H + j + 3], 0.f);
    ((float4*)carry)[idx] = cv;
}

__global__ void final_kernel(const float* __restrict__ b3, float* __restrict__ out) {
    int i = blockIdx.x * 256 + threadIdx.x;
    if (i < NE) {
        float v = g_acc[i] + b3[0];
        out[i] = 1.f / (1.f + expf(-v));
    }
}

extern "C" void kernel_launch(void* const* d_in, const int* in_sizes, int n_in,
                              void* d_out, int out_size) {
    const float* x     = (const float*)d_in[0];
    const int*   ei    = (const int*)  d_in[1];
    const float* Win   = (const float*)d_in[2];
    const float* Wrel  = (const float*)d_in[3];
    const float* brel  = (const float*)d_in[4];
    const float* Wroot = (const float*)d_in[5];
    const float* gamma = (const float*)d_in[6];
    const float* beta  = (const float*)d_in[7];
    const float* W1    = (const float*)d_in[8];
    const float* b1    = (const float*)d_in[9];
    const float* W2    = (const float*)d_in[10];
    const float* b2    = (const float*)d_in[11];
    const float* W3    = (const float*)d_in[12];
    const float* b3    = (const float*)d_in[13];
    float* out = (float*)d_out;

    float *h, *agg, *tmp, *acc;
    cudaGetSymbolAddress((void**)&h,   g_h);
    cudaGetSymbolAddress((void**)&agg, g_agg);
    cudaGetSymbolAddress((void**)&tmp, g_tmp);
    cudaGetSymbolAddress((void**)&acc, g_acc);

    const int* src = ei;
    const int* dst = ei + NE;

    // ---- CSR build (graph-capturable, deterministic result set) ----
    zero_cnt_kernel<<<(NN + 255) / 256, 256>>>();
    hist_kernel<<<(NE + 255) / 256, 256>>>(dst);
    scan_kernel<<<1, 1024>>>();
    fill_kernel<<<(NE + 255) / 256, 256>>>(src, dst);

    input_fc_kernel<<<NN * 64 / 256, 256>>>(x, Win, h);
    zero_acc_kernel<<<(NE + 255) / 256, 256>>>(acc);

    for (int l = 0; l < NL; l++) {
        aggregate_kernel<<<(NN * 64 + 255) / 256, 256>>>(h, agg);
        zero_stats_kernel<<<1, 512>>>();
        gemm_kernel<0, 0, 32, 1><<<dim3(391, 4), 256>>>(
            agg, h, nullptr, nullptr, nullptr,
            Wrel + (size_t)l * H * H, Wroot + (size_t)l * H * H, H,
            brel + l * H, tmp, NN, nullptr, nullptr);
        bn_prep_kernel<<<1, 256>>>(gamma + l * H, beta + l * H);
        bn_apply_kernel<<<NN * 64 / 256, 256>>>(h, tmp);
    }

    // P = h @ W1[:, :256]^T  -> agg ;  Q = h @ W1[:, 256:]^T -> tmp
    gemm_kernel<0, 0, 16, 0><<<dim3(391, 4), 256>>>(
        h, h, nullptr, nullptr, nullptr, W1, W1, 2 * H, nullptr, agg, NN, nullptr, nullptr);
    gemm_kernel<0, 0, 16, 0><<<dim3(391, 4), 256>>>(
        h, h, nullptr, nullptr, nullptr, W1 + H, W1 + H, 2 * H, nullptr, tmp, NN, nullptr, nullptr);

    // fused: z1 = relu(P[src]+Q[dst]+b1); z2 = relu(z1@W2^T + b2); acc += z2 . w3
    gemm_kernel<2, 2, 16, 0><<<dim3((NE + 127) / 128, 4), 256>>>(
        agg, tmp, src, dst, b1, W2, W2, H, b2, nullptr, NE, W3, acc);

    final_kernel<<<(NE + 255) / 256, 256>>>(b3, out);
}

// round 7
// speedup vs baseline: 2.4466x; 1.4425x over previous
#include <cuda_runtime.h>
#include <cuda_bf16.h>
#include <math.h>
#include <stdint.h>

#define NN 50000
#define NE 500000
#define H  256
#define NL 15
#define NSLOT 32   // 30 layer weights + W1a + W1b

// ---- scratch (device globals; no allocations allowed) ----
static __device__ float  g_h[(size_t)NN * H];     // carry (fp32)
static __device__ float  g_agg[(size_t)NN * H];   // later P (fp32)
static __device__ float  g_tmp[(size_t)NN * H];   // layer out; later Q (fp32)
static __device__ double g_stats[2 * H];
static __device__ float  g_bnp[2 * H];
static __device__ float  g_acc[NE];
static __device__ int    g_cnt[NN];
static __device__ int    g_rowptr[NN + 1];
static __device__ int    g_cursor[NN];
static __device__ int    g_csrsrc[NE];
// bf16 split buffers
static __device__ __nv_bfloat16 g_axh[(size_t)NN * H];  // agg hi
static __device__ __nv_bfloat16 g_axl[(size_t)NN * H];  // agg lo
static __device__ __nv_bfloat16 g_hxh[(size_t)NN * H];  // h hi
static __device__ __nv_bfloat16 g_hxl[(size_t)NN * H];  // h lo
static __device__ __nv_bfloat16 g_wbh[(size_t)NSLOT * H * H];
static __device__ __nv_bfloat16 g_wbl[(size_t)NSLOT * H * H];

typedef unsigned long long u64;

__device__ __forceinline__ uint32_t smem_u32(const void* p) {
    uint32_t a;
    asm("{ .reg .u64 t; cvta.to.shared.u64 t, %1; cvt.u32.u64 %0, t; }" : "=r"(a) : "l"(p));
    return a;
}

// f32x2 helpers (edge GEMM)
__device__ __forceinline__ u64 pk2(float lo, float hi) {
    u64 r; asm("mov.b64 %0, {%1, %2};" : "=l"(r) : "f"(lo), "f"(hi)); return r;
}
__device__ __forceinline__ void fma2(u64 &c, u64 a, u64 b) {
    asm("fma.rn.f32x2 %0, %1, %2, %0;" : "+l"(c) : "l"(a), "l"(b));
}
__device__ __forceinline__ void upk(u64 v, float &a, float &b) {
    asm("mov.b64 {%0, %1}, %2;" : "=f"(a), "=f"(b) : "l"(v));
}

__device__ __forceinline__ void bsplit(float x, __nv_bfloat16 &hi, __nv_bfloat16 &lo) {
    hi = __float2bfloat16(x);
    lo = __float2bfloat16(x - __bfloat162float(hi));
}

#define LDMX4(r0, r1, r2, r3, ad) \
    asm volatile("ldmatrix.sync.aligned.m8n8.x4.shared.b16 {%0,%1,%2,%3}, [%4];" \
        : "=r"(r0), "=r"(r1), "=r"(r2), "=r"(r3) : "r"(ad))

#define MMA_BF16(d, a, b0, b1) \
    asm volatile("mma.sync.aligned.m16n8k16.row.col.f32.bf16.bf16.f32 " \
        "{%0,%1,%2,%3}, {%4,%5,%6,%7}, {%8,%9}, {%0,%1,%2,%3};" \
        : "+f"((d)[0]), "+f"((d)[1]), "+f"((d)[2]), "+f"((d)[3]) \
        : "r"((a)[0]), "r"((a)[1]), "r"((a)[2]), "r"((a)[3]), "r"(b0), "r"(b1))

// ================= CSR construction =================
__global__ void zero_cnt_kernel() {
    int i = blockIdx.x * 256 + threadIdx.x;
    if (i < NN) g_cnt[i] = 0;
}
__global__ void hist_kernel(const int* __restrict__ dst) {
    int e = blockIdx.x * 256 + threadIdx.x;
    if (e < NE) atomicAdd(&g_cnt[dst[e]], 1);
}
__global__ void scan_kernel() {
    __shared__ int partial[1024];
    const int CH = (NN + 1023) / 1024;
    int t = threadIdx.x;
    int base = t * CH;
    int s = 0;
    for (int i = 0; i < CH; i++) {
        int idx = base + i;
        if (idx < NN) s += g_cnt[idx];
    }
    partial[t] = s;
    __syncthreads();
    for (int off = 1; off < 1024; off <<= 1) {
        int v = (t >= off) ? partial[t - off] : 0;
        __syncthreads();
        partial[t] += v;
        __syncthreads();
    }
    int ex = partial[t] - s;
    for (int i = 0; i < CH; i++) {
        int idx = base + i;
        if (idx < NN) {
            g_rowptr[idx] = ex;
            g_cursor[idx] = ex;
            ex += g_cnt[idx];
        }
    }
    if (t == 1023) g_rowptr[NN] = NE;
}
__global__ void fill_kernel(const int* __restrict__ src, const int* __restrict__ dst) {
    int e = blockIdx.x * 256 + threadIdx.x;
    if (e < NE) {
        int pos = atomicAdd(&g_cursor[dst[e]], 1);
        g_csrsrc[pos] = src[e];
    }
}

// ================= weight split (once) =================
// slots 0..29: layer l rel = 2l, root = 2l+1; 30 = W1[:, :256]; 31 = W1[:, 256:]
__global__ void wsplit_kernel(const float* __restrict__ Wrel, const float* __restrict__ Wroot,
                              const float* __restrict__ W1) {
    int idx = blockIdx.x * 256 + threadIdx.x;      // float4 granule
    if (idx >= NSLOT * H * H / 4) return;
    int slot = idx / (H * H / 4);
    int rem = idx - slot * (H * H / 4);
    int j = rem / (H / 4);
    int k4 = (rem % (H / 4)) * 4;
    const float* s;
    if (slot < 30) {
        int l = slot >> 1;
        s = ((slot & 1) ? Wroot : Wrel) + (size_t)l * H * H + (size_t)j * H + k4;
    } else if (slot == 30) {
        s = W1 + (size_t)j * (2 * H) + k4;
    } else {
        s = W1 + (size_t)j * (2 * H) + H + k4;
    }
    float4 v = *(const float4*)s;
    size_t o = (size_t)slot * H * H + (size_t)j * H + k4;
    __nv_bfloat16 h0, l0, h1, l1, h2, l2, h3, l3;
    bsplit(v.x, h0, l0); bsplit(v.y, h1, l1); bsplit(v.z, h2, l2); bsplit(v.w, h3, l3);
    g_wbh[o] = h0; g_wbh[o+1] = h1; g_wbh[o+2] = h2; g_wbh[o+3] = h3;
    g_wbl[o] = l0; g_wbl[o+1] = l1; g_wbl[o+2] = l2; g_wbl[o+3] = l3;
}

// ---- h = x @ W_in^T (+ split) ----
__global__ void input_fc_kernel(const float* __restrict__ x, const float* __restrict__ Win,
                                float* __restrict__ h) {
    __shared__ float w0[H], w1[H];
    int tid = threadIdx.x;
    w0[tid] = Win[tid * 2];
    w1[tid] = Win[tid * 2 + 1];
    __syncthreads();
    int idx = blockIdx.x * 256 + tid;
    if (idx < NN * 64) {
        int n = idx >> 6;
        int j = (idx & 63) * 4;
        float2 xv = *(const float2*)(x + (size_t)n * 2);
        float4 o;
        o.x = xv.x * w0[j + 0] + xv.y * w1[j + 0];
        o.y = xv.x * w0[j + 1] + xv.y * w1[j + 1];
        o.z = xv.x * w0[j + 2] + xv.y * w1[j + 2];
        o.w = xv.x * w0[j + 3] + xv.y * w1[j + 3];
        ((float4*)h)[idx] = o;
        size_t e = (size_t)n * H + j;
        __nv_bfloat16 hh[4], ll[4];
        bsplit(o.x, hh[0], ll[0]); bsplit(o.y, hh[1], ll[1]);
        bsplit(o.z, hh[2], ll[2]); bsplit(o.w, hh[3], ll[3]);
        #pragma unroll
        for (int q = 0; q < 4; q++) { g_hxh[e+q] = hh[q]; g_hxl[e+q] = ll[q]; }
    }
}

__global__ void zero_acc_kernel(float* __restrict__ acc) {
    int i = blockIdx.x * 256 + threadIdx.x;
    if (i < NE) acc[i] = 0.f;
}

// ---- CSR aggregation -> bf16 split ----
__global__ void aggregate_kernel(const float* __restrict__ h) {
    int t = blockIdx.x * 256 + threadIdx.x;
    int node = t >> 6;
    int lane = t & 63;
    if (node >= NN) return;
    int b = g_rowptr[node], e = g_rowptr[node + 1];
    float4 s = make_float4(0.f, 0.f, 0.f, 0.f);
    for (int j = b; j < e; j++) {
        int sn = __ldg(g_csrsrc + j);
        float4 v = __ldg((const float4*)(h + (size_t)sn * H) + lane);
        s.x += v.x; s.y += v.y; s.z += v.z; s.w += v.w;
    }
    size_t o = (size_t)node * H + lane * 4;
    __nv_bfloat16 hh[4], ll[4];
    bsplit(s.x, hh[0], ll[0]); bsplit(s.y, hh[1], ll[1]);
    bsplit(s.z, hh[2], ll[2]); bsplit(s.w, hh[3], ll[3]);
    #pragma unroll
    for (int q = 0; q < 4; q++) { g_axh[o+q] = hh[q]; g_axl[o+q] = ll[q]; }
}

// ================= bf16 split-2 mma.sync GEMM =================
// C[m][j] = sum_phase A_phase[m][:] . B_phase[j][:]  (+bias), K=256 per phase
// block 128x128, 128 threads, 4 warps of 64x64. BK=64 per chunk.
// smem: Ahi(16K) Alo(16K) Bhi(16K) Blo(16K); epilogue reuses as 128x132 f32 tile.
#define GT_DYN 69696   // max(65536, 128*132*4=67584) + pad

template<int PHASES, int STATS>
__global__ void __launch_bounds__(128, 2) bf16_gemm(
    const __nv_bfloat16* __restrict__ Ah0, const __nv_bfloat16* __restrict__ Al0,
    const __nv_bfloat16* __restrict__ Ah1, const __nv_bfloat16* __restrict__ Al1,
    const __nv_bfloat16* __restrict__ Bh, const __nv_bfloat16* __restrict__ Bl,
    const float* __restrict__ bias,
    float* __restrict__ C, int M)
{
    extern __shared__ char sm[];
    __shared__ float sbias[128];
    const uint32_t sb = smem_u32(sm);
    const int tid = threadIdx.x;
    const int w = tid >> 5;
    const int l = tid & 31;
    const int m0 = blockIdx.x * 128;
    const int j0 = blockIdx.y * 128;
    const int wm0 = (w >> 1) * 64;
    const int wn0 = (w & 1) * 64;

    if (tid < 128) sbias[tid] = bias ? bias[j0 + tid] : 0.f;

    float d[4][8][4];
    #pragma unroll
    for (int mt = 0; mt < 4; mt++)
        #pragma unroll
        for (int ng = 0; ng < 8; ng++)
            #pragma unroll
            for (int q = 0; q < 4; q++) d[mt][ng][q] = 0.f;

    const int rb = w * 32 + (l >> 3);   // staging row base (step 4)
    const int cc = l & 7;               // 16B chunk within row

    const int NCH = PHASES * 4;
    for (int c = 0; c < NCH; c++) {
        const int phase = (PHASES == 2) ? (c >> 2) : 0;
        const int ko = (c & 3) * 64;
        const __nv_bfloat16* pAh = phase ? Ah1 : Ah0;
        const __nv_bfloat16* pAl = phase ? Al1 : Al0;
        const __nv_bfloat16* pBh = Bh + (size_t)phase * H * H;
        const __nv_bfloat16* pBl = Bl + (size_t)phase * H * H;

        __syncthreads();   // previous compute done before overwrite
        // stage A (guarded) and B
        #pragma unroll
        for (int t4 = 0; t4 < 2; t4++) {
            const __nv_bfloat16* src = t4 ? pAl : pAh;
            uint32_t base = sb + t4 * 16384;
            #pragma unroll
            for (int i = 0; i < 8; i++) {
                int r = rb + i * 4;
                int gr = m0 + r;
                uint4 v = make_uint4(0u, 0u, 0u, 0u);
                if (gr < M) v = *(const uint4*)(src + (size_t)gr * H + ko + cc * 8);
                *(uint4*)((char*)sm + (base - sb) + r * 128 + ((cc ^ (r & 7)) * 16)) = v;
            }
        }
        #pragma unroll
        for (int t4 = 0; t4 < 2; t4++) {
            const __nv_bfloat16* src = t4 ? pBl : pBh;
            uint32_t off = 32768 + t4 * 16384;
            #pragma unroll
            for (int i = 0; i < 8; i++) {
                int r = rb + i * 4;
                uint4 v = *(const uint4*)(src + (size_t)(j0 + r) * H + ko + cc * 8);
                *(uint4*)((char*)sm + off + r * 128 + ((cc ^ (r & 7)) * 16)) = v;
            }
        }
        __syncthreads();

        #pragma unroll
        for (int ks = 0; ks < 4; ks++) {
            // A fragments: 4 m-tiles, hi+lo
            uint32_t ahi[4][4], alo[4][4];
            const int ra = wm0 + (l & 15);
            const int kga = ks * 2 + (l >> 4);
            #pragma unroll
            for (int mt = 0; mt < 4; mt++) {
                int row = ra + mt * 16;
                uint32_t ad = sb + row * 128 + ((kga ^ (row & 7)) * 16);
                LDMX4(ahi[mt][0], ahi[mt][1], ahi[mt][2], ahi[mt][3], ad);
                LDMX4(alo[mt][0], alo[mt][1], alo[mt][2], alo[mt][3], ad + 16384);
            }
            const int rbn = wn0 + (l & 7) + ((l >> 4) << 3);
            const int kgb = ks * 2 + ((l >> 3) & 1);
            #pragma unroll
            for (int nb = 0; nb < 4; nb++) {
                int row = rbn + nb * 16;
                uint32_t bd = sb + 32768 + row * 128 + ((kgb ^ (row & 7)) * 16);
                uint32_t bhi[4], blo[4];
                LDMX4(bhi[0], bhi[1], bhi[2], bhi[3], bd);
                LDMX4(blo[0], blo[1], blo[2], blo[3], bd + 16384);
                #pragma unroll
                for (int g = 0; g < 2; g++) {
                    int ng = nb * 2 + g;
                    #pragma unroll
                    for (int mt = 0; mt < 4; mt++) {
                        MMA_BF16(d[mt][ng], ahi[mt], bhi[2*g], bhi[2*g+1]);
                        MMA_BF16(d[mt][ng], ahi[mt], blo[2*g], blo[2*g+1]);
                        MMA_BF16(d[mt][ng], alo[mt], bhi[2*g], bhi[2*g+1]);
                    }
                }
            }
        }
    }
    __syncthreads();

    // epilogue: accums -> smem tile (128 x 132 f32)
    float* tile = (float*)sm;
    {
        const int gid = l >> 2;
        const int tid4 = l & 3;
        #pragma unroll
        for (int mt = 0; mt < 4; mt++) {
            int r0 = wm0 + mt * 16 + gid;
            #pragma unroll
            for (int ng = 0; ng < 8; ng++) {
                int col = wn0 + ng * 8 + tid4 * 2;
                tile[r0 * 132 + col]       = d[mt][ng][0];
                tile[r0 * 132 + col + 1]   = d[mt][ng][1];
                tile[(r0+8) * 132 + col]   = d[mt][ng][2];
                tile[(r0+8) * 132 + col+1] = d[mt][ng][3];
            }
        }
    }
    __syncthreads();

    // store C (+bias) from tile
    #pragma unroll 4
    for (int p = 0; p < 32; p++) {
        int r = p * 4 + (tid >> 5);
        int cq = (tid & 31) * 4;
        float4 v = *(float4*)(tile + r * 132 + cq);
        v.x += sbias[cq]; v.y += sbias[cq+1]; v.z += sbias[cq+2]; v.w += sbias[cq+3];
        int gr = m0 + r;
        if (gr < M) *(float4*)(C + (size_t)gr * H + j0 + cq) = v;
    }

    if (STATS) {
        if (tid < 128) {
            int j = tid;
            float b = sbias[j];
            int R = M - m0; if (R > 128) R = 128;
            float s = 0.f, q = 0.f;
            for (int r = 0; r < R; r++) {
                float v = tile[r * 132 + j] + b;
                s += v;
                q += v * v;
            }
            atomicAdd(&g_stats[j0 + j], (double)s);
            atomicAdd(&g_stats[H + j0 + j], (double)q);
        }
    }
}

// ================= f32x2 edge GEMM (AMODE2/EPI2 only) =================
__global__ void __launch_bounds__(256) edge_gemm_kernel(
    const float* __restrict__ A0, const float* __restrict__ A1,
    const int* __restrict__ idx0, const int* __restrict__ idx1,
    const float* __restrict__ biasA,
    const float* __restrict__ B0,
    const float* __restrict__ bias,
    int M, const float* __restrict__ w3, float* __restrict__ accOut)
{
    __shared__ __align__(16) float As[16][132];
    __shared__ __align__(16) float Bs[16][68];
    __shared__ int sIdx[2][128];
    const int tid = threadIdx.x;
    const int tx = tid & 15, ty = tid >> 4;
    const int m0 = blockIdx.x * 128;
    const int j0 = blockIdx.y * 64;

    if (tid < 128) {
        int r = min(m0 + tid, M - 1);
        sIdx[0][tid] = idx0[r];
        sIdx[1][tid] = idx1[r];
    }
    __syncthreads();

    u64 acc[4][4];
    #pragma unroll
    for (int i = 0; i < 4; i++)
        #pragma unroll
        for (int j = 0; j < 4; j++) acc[i][j] = 0ull;

    const int bm  = tid >> 2;
    const int bkv = tid & 3;

    for (int kt = 0; kt < 16; ++kt) {
        const int kof = kt * 16;
        #pragma unroll
        for (int q = 0; q < 2; q++) {
            int m = bm + q * 64;
            int rs = sIdx[0][m], rd = sIdx[1][m];
            float4 p  = *(const float4*)(A0 + (size_t)rs * H + kof + bkv * 4);
            float4 qq = *(const float4*)(A1 + (size_t)rd * H + kof + bkv * 4);
            float4 bb = *(const float4*)(biasA + kof + bkv * 4);
            float4 v;
            v.x = fmaxf(p.x + qq.x + bb.x, 0.f);
            v.y = fmaxf(p.y + qq.y + bb.y, 0.f);
            v.z = fmaxf(p.z + qq.z + bb.z, 0.f);
            v.w = fmaxf(p.w + qq.w + bb.w, 0.f);
            As[bkv * 4 + 0][m] = v.x;
            As[bkv * 4 + 1][m] = v.y;
            As[bkv * 4 + 2][m] = v.z;
            As[bkv * 4 + 3][m] = v.w;
        }
        {
            float4 v = *(const float4*)(B0 + (size_t)(j0 + bm) * H + kof + bkv * 4);
            Bs[bkv * 4 + 0][bm] = v.x;
            Bs[bkv * 4 + 1][bm] = v.y;
            Bs[bkv * 4 + 2][bm] = v.z;
            Bs[bkv * 4 + 3][bm] = v.w;
        }
        __syncthreads();
        #pragma unroll
        for (int kk = 0; kk < 16; ++kk) {
            const ulonglong2* ap = (const ulonglong2*)(&As[kk][ty * 8]);
            ulonglong2 aA = ap[0], aB = ap[1];
            u64 ar[4] = { aA.x, aA.y, aB.x, aB.y };
            float4 b = *(const float4*)(&Bs[kk][tx * 4]);
            u64 bd[4] = { pk2(b.x, b.x), pk2(b.y, b.y), pk2(b.z, b.z), pk2(b.w, b.w) };
            #pragma unroll
            for (int j = 0; j < 4; j++)
                #pragma unroll
                for (int i = 0; i < 4; i++)
                    fma2(acc[i][j], ar[i], bd[j]);
        }
        __syncthreads();
    }

    float c[8][4];
    #pragma unroll
    for (int i = 0; i < 4; i++)
        #pragma unroll
        for (int j = 0; j < 4; j++)
            upk(acc[i][j], c[2 * i][j], c[2 * i + 1][j]);

    float4 bs = *(const float4*)(bias + j0 + tx * 4);
    float4 wv = *(const float4*)(w3 + j0 + tx * 4);
    #pragma unroll
    for (int i = 0; i < 8; i++) {
        float p = fmaxf(c[i][0] + bs.x, 0.f) * wv.x
                + fmaxf(c[i][1] + bs.y, 0.f) * wv.y
                + fmaxf(c[i][2] + bs.z, 0.f) * wv.z
                + fmaxf(c[i][3] + bs.w, 0.f) * wv.w;
        p += __shfl_xor_sync(0xffffffffu, p, 1);
        p += __shfl_xor_sync(0xffffffffu, p, 2);
        p += __shfl_xor_sync(0xffffffffu, p, 4);
        p += __shfl_xor_sync(0xffffffffu, p, 8);
        int r = m0 + ty * 8 + i;
        if (tx == 0 && r < M) atomicAdd(accOut + r, p);
    }
}

// ---- BN ----
__global__ void zero_stats_kernel() {
    g_stats[threadIdx.x] = 0.0;
}

__global__ void bn_prep_kernel(const float* __restrict__ gamma, const float* __restrict__ beta) {
    int j = threadIdx.x;
    double mean = g_stats[j] * (1.0 / NN);
    double var  = g_stats[H + j] * (1.0 / NN) - mean * mean;
    double inv  = 1.0 / sqrt(var + 1e-5);
    double sc   = (double)gamma[j] * inv;
    g_bnp[j]     = (float)sc;
    g_bnp[H + j] = (float)((double)beta[j] - mean * sc);
}

// carry += relu(T*scale + offset); also refresh h bf16 split
__global__ void bn_apply_kernel(float* __restrict__ carry, const float* __restrict__ T) {
    int idx = blockIdx.x * 256 + threadIdx.x;
    if (idx >= NN * 64) return;
    int j = (idx & 63) * 4;
    float4 t  = ((const float4*)T)[idx];
    float4 cv = ((float4*)carry)[idx];
    cv.x += fmaxf(t.x * g_bnp[j + 0] + g_bnp[H + j + 0], 0.f);
    cv.y += fmaxf(t.y * g_bnp[j + 1] + g_bnp[H + j + 1], 0.f);
    cv.z += fmaxf(t.z * g_bnp[j + 2] + g_bnp[H + j + 2], 0.f);
    cv.w += fmaxf(t.w * g_bnp[j + 3] + g_bnp[H + j + 3], 0.f);
    ((float4*)carry)[idx] = cv;
    size_t e = (size_t)idx * 4;
    __nv_bfloat16 hh[4], ll[4];
    bsplit(cv.x, hh[0], ll[0]); bsplit(cv.y, hh[1], ll[1]);
    bsplit(cv.z, hh[2], ll[2]); bsplit(cv.w, hh[3], ll[3]);
    #pragma unroll
    for (int q = 0; q < 4; q++) { g_hxh[e+q] = hh[q]; g_hxl[e+q] = ll[q]; }
}

__global__ void final_kernel(const float* __restrict__ b3, float* __restrict__ out) {
    int i = blockIdx.x * 256 + threadIdx.x;
    if (i < NE) {
        float v = g_acc[i] + b3[0];
        out[i] = 1.f / (1.f + expf(-v));
    }
}

extern "C" void kernel_launch(void* const* d_in, const int* in_sizes, int n_in,
                              void* d_out, int out_size) {
    const float* x     = (const float*)d_in[0];
    const int*   ei    = (const int*)  d_in[1];
    const float* Win   = (const float*)d_in[2];
    const float* Wrel  = (const float*)d_in[3];
    const float* brel  = (const float*)d_in[4];
    const float* Wroot = (const float*)d_in[5];
    const float* gamma = (const float*)d_in[6];
    const float* beta  = (const float*)d_in[7];
    const float* W1    = (const float*)d_in[8];
    const float* b1    = (const float*)d_in[9];
    const float* W2    = (const float*)d_in[10];
    const float* b2    = (const float*)d_in[11];
    const float* W3    = (const float*)d_in[12];
    const float* b3    = (const float*)d_in[13];
    float* out = (float*)d_out;

    float *h, *P, *Q, *acc;
    cudaGetSymbolAddress((void**)&h,   g_h);
    cudaGetSymbolAddress((void**)&P,   g_agg);
    cudaGetSymbolAddress((void**)&Q,   g_tmp);
    cudaGetSymbolAddress((void**)&acc, g_acc);
    __nv_bfloat16 *axh, *axl, *hxh, *hxl, *wbh, *wbl;
    cudaGetSymbolAddress((void**)&axh, g_axh);
    cudaGetSymbolAddress((void**)&axl, g_axl);
    cudaGetSymbolAddress((void**)&hxh, g_hxh);
    cudaGetSymbolAddress((void**)&hxl, g_hxl);
    cudaGetSymbolAddress((void**)&wbh, g_wbh);
    cudaGetSymbolAddress((void**)&wbl, g_wbl);

    const int* src = ei;
    const int* dst = ei + NE;

    cudaFuncSetAttribute(bf16_gemm<2, 1>, cudaFuncAttributeMaxDynamicSharedMemorySize, GT_DYN);
    cudaFuncSetAttribute(bf16_gemm<1, 0>, cudaFuncAttributeMaxDynamicSharedMemorySize, GT_DYN);

    // CSR build
    zero_cnt_kernel<<<(NN + 255) / 256, 256>>>();
    hist_kernel<<<(NE + 255) / 256, 256>>>(dst);
    scan_kernel<<<1, 1024>>>();
    fill_kernel<<<(NE + 255) / 256, 256>>>(src, dst);

    // weight split + input fc
    wsplit_kernel<<<(NSLOT * H * H / 4 + 255) / 256, 256>>>(Wrel, Wroot, W1);
    input_fc_kernel<<<NN * 64 / 256, 256>>>(x, Win, h);
    zero_acc_kernel<<<(NE + 255) / 256, 256>>>(acc);

    for (int l = 0; l < NL; l++) {
        aggregate_kernel<<<(NN * 64 + 255) / 256, 256>>>(h);
        zero_stats_kernel<<<1, 512>>>();
        bf16_gemm<2, 1><<<dim3(391, 2), 128, GT_DYN>>>(
            axh, axl, hxh, hxl,
            wbh + (size_t)(2 * l) * H * H, wbl + (size_t)(2 * l) * H * H,
            brel + l * H, Q /*g_tmp*/, NN);
        bn_prep_kernel<<<1, 256>>>(gamma + l * H, beta + l * H);
        bn_apply_kernel<<<NN * 64 / 256, 256>>>(h, Q);
    }

    // P = h @ W1a^T ; Q = h @ W1b^T
    bf16_gemm<1, 0><<<dim3(391, 2), 128, GT_DYN>>>(
        hxh, hxl, nullptr, nullptr,
        wbh + (size_t)30 * H * H, wbl + (size_t)30 * H * H, nullptr, P, NN);
    bf16_gemm<1, 0><<<dim3(391, 2), 128, GT_DYN>>>(
        hxh, hxl, nullptr, nullptr,
        wbh + (size_t)31 * H * H, wbl + (size_t)31 * H * H, nullptr, Q, NN);

    // fused edge MLP: z1 = relu(P[src]+Q[dst]+b1); z2 = relu(z1@W2^T+b2); acc += z2 . w3
    edge_gemm_kernel<<<dim3((NE + 127) / 128, 4), 256>>>(
        P, Q, src, dst, b1, W2, b2, NE, W3, acc);

    final_kernel<<<(NE + 255) / 256, 256>>>(b3, out);
}